// round 3
// baseline (speedup 1.0000x reference)
#include <cuda_runtime.h>

// ---------------- static problem config -------------------------------------
#define NUM_SEQS   8
#define QLEN       128
#define NQH        32
#define NKVH       8
#define HDIM       128
#define BLKSZ      16
#define MAXBLOCKS  128
#define NSEG       4
#define SEGTILE    32

// ---------------- tiling ----------------------------------------------------
#define TQ    64      // q rows per CTA
#define TL    64      // keys per stage (4 paged blocks)
#define NTHR  256     // 8 warps

#define QT2S  136     // qT2 row stride (2*64 dup + pad), floats
#define VSS   132     // vs row stride [l][dv], floats

// smem offsets (floats)
#define SM_QT2 0
#define SM_K   (SM_QT2 + HDIM*QT2S)   // 17408
#define SM_V   (SM_K  + HDIM*TL)      // 25600
#define SM_P   (SM_V  + TL*VSS)       // 34048
#define SM_TOT (SM_P  + TL*128)       // 42240 floats = 168960 B

typedef unsigned long long u64;

__device__ __forceinline__ u64 pk2(float a, float b) {
    u64 r; asm("mov.b64 %0,{%1,%2};" : "=l"(r) : "f"(a), "f"(b)); return r;
}
__device__ __forceinline__ void up2(u64 v, float& a, float& b) {
    asm("mov.b64 {%0,%1},%2;" : "=f"(a), "=f"(b) : "l"(v));
}
__device__ __forceinline__ u64 ffma2(u64 a, u64 b, u64 c) {
    u64 d; asm("fma.rn.f32x2 %0,%1,%2,%3;" : "=l"(d) : "l"(a), "l"(b), "l"(c)); return d;
}
__device__ __forceinline__ u64 fmul2(u64 a, u64 b) {
    u64 d; asm("mul.rn.f32x2 %0,%1,%2;" : "=l"(d) : "l"(a), "l"(b)); return d;
}

extern __shared__ float sm[];

__global__ void __launch_bounds__(NTHR, 1) Model_3470333575380_kernel(
    const float* __restrict__ query,
    const float* __restrict__ key_cache,
    const float* __restrict__ value_cache,
    const int*   __restrict__ block_tables,
    const int*   __restrict__ seq_lens,
    float*       __restrict__ out)
{
    const float scale   = 0.08838834764831845f;   // 1/sqrt(128)
    const float softcap = 30.0f;
    const float inv2cap = 2.0f / softcap;

    float* qT2 = sm + SM_QT2;   // [128 d][2*64 q dup]
    float* ks  = sm + SM_K;     // [128 d][64 l], chunk-swizzled by (d&7)
    float* vs  = sm + SM_V;     // [64 l][128 dv + pad]
    float* ps2 = sm + SM_P;     // [64 l][2*64 q dup], chunk-swizzled by ((l>>2)&7)

    const int tid  = threadIdx.x;
    const int lane = tid & 31;
    const int w    = tid >> 5;        // warp id == q-group (8 q rows per warp)

    const int cta = blockIdx.x;
    const int sp  = cta & 1;                  // segment pair {2sp, 2sp+1}
    const int qt  = (cta >> 1) & 1;
    const int h   = (cta >> 2) & (NQH - 1);
    const int s   = cta >> 7;
    const int hkv = h >> 2;

    const int seq_len = seq_lens[s];
    const int ctx     = seq_len - QLEN;
    const int span    = ((seq_len + NSEG*SEGTILE - 1) / (NSEG*SEGTILE)) * SEGTILE; // 512
    const int n_stages = span / TL;           // 8

    const int q0     = qt * TQ;
    const int t_base = s * QLEN + q0;

    // ---- load q tile (pre-scaled), duplicated pairs, [d][2q] ----
    for (int idx = tid; idx < TQ * HDIM; idx += NTHR) {
        int i = idx >> 7;              // q row 0..63
        int d = idx & (HDIM - 1);
        float v = query[((size_t)(t_base + i)*NQH + h)*HDIM + d] * scale;
        qT2[d*QT2S + 2*i]     = v;
        qT2[d*QT2S + 2*i + 1] = v;
    }

    const size_t kv_base4_stride = (size_t)(HDIM * BLKSZ / 4);  // float4 per (blk,head)
    const float4* kc4 = reinterpret_cast<const float4*>(key_cache);
    const float4* vc4 = reinterpret_cast<const float4*>(value_cache);

    u64 accP[8][2];     // 8 q rows x 4 dv (2 pairs); dv = lane*4 .. +3
    float m_prev[8];

    for (int sg = 0; sg < 2; sg++) {
        const int seg = 2*sp + sg;
        #pragma unroll
        for (int qq = 0; qq < 8; qq++) {
            accP[qq][0] = 0ull; accP[qq][1] = 0ull;
            m_prev[qq]  = -1e30f;
        }

        for (int st = 0; st < n_stages; st++) {
            const int l_base = seg * span + st * TL;

            // ---- stage K/V (4 paged blocks of 16 keys) ----
            {
                const int* bt = block_tables + s * MAXBLOCKS + (l_base >> 4);
                #pragma unroll
                for (int it = 0; it < (4*512)/NTHR; it++) {
                    int f  = it * NTHR + tid;      // 0..2047 float4s
                    int j  = f >> 9;               // block 0..3
                    int fi = f & 511;
                    int pb = bt[j];
                    size_t b4 = ((size_t)pb * NKVH + hkv) * kv_base4_stride;
                    int d  = fi >> 2;
                    int cl = fi & 3;
                    float4 k4 = kc4[b4 + fi];
                    int c = (j*4 + cl) ^ (d & 7);
                    *reinterpret_cast<float4*>(ks + d*TL + (c << 2)) = k4;
                    float4 v4 = vc4[b4 + fi];
                    int lr = j*16 + cl*4;
                    vs[(lr+0)*VSS + d] = v4.x;
                    vs[(lr+1)*VSS + d] = v4.y;
                    vs[(lr+2)*VSS + d] = v4.z;
                    vs[(lr+3)*VSS + d] = v4.w;
                }
            }
            __syncthreads();

            // ---- QK: 8q x 2l per thread (l = lane*2, lane*2+1) ----
            u64 acc2[8];
            #pragma unroll
            for (int qq = 0; qq < 8; qq++) acc2[qq] = 0ull;
            {
                const float* qbase = qT2 + w * 16;
                const int koff = (lane & 1) << 1;
                #pragma unroll 4
                for (int d = 0; d < HDIM; d++) {
                    int c = (lane >> 1) ^ (d & 7);
                    u64 k2 = *reinterpret_cast<const u64*>(ks + d*TL + (c << 2) + koff);
                    const float* qr = qbase + d*QT2S;
                    ulonglong2 qa = *reinterpret_cast<const ulonglong2*>(qr);
                    ulonglong2 qb = *reinterpret_cast<const ulonglong2*>(qr + 4);
                    ulonglong2 qc = *reinterpret_cast<const ulonglong2*>(qr + 8);
                    ulonglong2 qd = *reinterpret_cast<const ulonglong2*>(qr + 12);
                    acc2[0] = ffma2(qa.x, k2, acc2[0]);
                    acc2[1] = ffma2(qa.y, k2, acc2[1]);
                    acc2[2] = ffma2(qb.x, k2, acc2[2]);
                    acc2[3] = ffma2(qb.y, k2, acc2[3]);
                    acc2[4] = ffma2(qc.x, k2, acc2[4]);
                    acc2[5] = ffma2(qc.y, k2, acc2[5]);
                    acc2[6] = ffma2(qd.x, k2, acc2[6]);
                    acc2[7] = ffma2(qd.y, k2, acc2[7]);
                }
            }

            // ---- softcap + causal + online max (registers/shuffles only) ----
            float p0a[8], p1a[8], r_[8];
            {
                const int labs0 = l_base + lane*2;
                #pragma unroll
                for (int qq = 0; qq < 8; qq++) {
                    float s0, s1; up2(acc2[qq], s0, s1);
                    float e0 = __expf(s0 * inv2cap);
                    s0 = softcap * __fdividef(e0 - 1.0f, e0 + 1.0f);
                    float e1 = __expf(s1 * inv2cap);
                    s1 = softcap * __fdividef(e1 - 1.0f, e1 + 1.0f);
                    const int kmax = ctx + q0 + w*8 + qq;
                    s0 = (labs0     <= kmax) ? s0 : -3.0e38f;
                    s1 = (labs0 + 1 <= kmax) ? s1 : -3.0e38f;
                    float rm = fmaxf(s0, s1);
                    #pragma unroll
                    for (int o = 16; o >= 1; o >>= 1)
                        rm = fmaxf(rm, __shfl_xor_sync(0xffffffffu, rm, o));
                    float mo = m_prev[qq];
                    float mn = fmaxf(mo, rm);
                    r_[qq] = __expf(mo - mn);
                    m_prev[qq] = mn;
                    p0a[qq] = __expf(s0 - mn);
                    p1a[qq] = __expf(s1 - mn);
                }
            }

            // ---- store p duplicated pairs to ps2 (swizzled) ----
            {
                const int l0 = lane * 2;
                const int sw = (lane >> 1) & 7;       // (l0>>2)&7 == (l1>>2)&7
                float* r0p = ps2 + l0 * 128;
                float* r1p = r0p + 128;
                #pragma unroll
                for (int cc = 0; cc < 4; cc++) {
                    int ch = (((w*4 + cc) ^ sw) << 2);
                    float a0 = p0a[2*cc], b0 = p0a[2*cc+1];
                    float a1 = p1a[2*cc], b1 = p1a[2*cc+1];
                    *reinterpret_cast<float4*>(r0p + ch) = make_float4(a0, a0, b0, b0);
                    *reinterpret_cast<float4*>(r1p + ch) = make_float4(a1, a1, b1, b1);
                }
            }

            // ---- rescale accumulators ----
            #pragma unroll
            for (int qq = 0; qq < 8; qq++) {
                u64 r2 = pk2(r_[qq], r_[qq]);
                accP[qq][0] = fmul2(accP[qq][0], r2);
                accP[qq][1] = fmul2(accP[qq][1], r2);
            }
            __syncthreads();

            // ---- PV: 8q x 4dv per thread (dv = lane*4..+3), over 64 keys ----
            {
                const float* vbase = vs + lane * 4;
                #pragma unroll 2
                for (int l = 0; l < TL; l++) {
                    const int sw = (l >> 2) & 7;
                    const float* pr = ps2 + l * 128;
                    ulonglong2 v2 = *reinterpret_cast<const ulonglong2*>(vbase + l*VSS);
                    u64 pp[8];
                    #pragma unroll
                    for (int cc = 0; cc < 4; cc++) {
                        ulonglong2 t = *reinterpret_cast<const ulonglong2*>(
                            pr + (((w*4 + cc) ^ sw) << 2));
                        pp[2*cc]   = t.x;
                        pp[2*cc+1] = t.y;
                    }
                    #pragma unroll
                    for (int qq = 0; qq < 8; qq++) {
                        accP[qq][0] = ffma2(pp[qq], v2.x, accP[qq][0]);
                        accP[qq][1] = ffma2(pp[qq], v2.y, accP[qq][1]);
                    }
                }
            }
            __syncthreads();
        } // stages

        // ---- write this segment's (unnormalized) accumulator ----
        #pragma unroll
        for (int qq = 0; qq < 8; qq++) {
            int t = t_base + w*8 + qq;
            float4 o;
            up2(accP[qq][0], o.x, o.y);
            up2(accP[qq][1], o.z, o.w);
            *reinterpret_cast<float4*>(
                out + (((size_t)t*NQH + h)*NSEG + seg)*HDIM + lane*4) = o;
        }
    } // segment pair
}

extern "C" void kernel_launch(void* const* d_in, const int* in_sizes, int n_in,
                              void* d_out, int out_size) {
    (void)in_sizes; (void)n_in; (void)out_size;
    const float* query        = (const float*)d_in[0];
    const float* key_cache    = (const float*)d_in[1];
    const float* value_cache  = (const float*)d_in[2];
    const int*   block_tables = (const int*)d_in[3];
    const int*   seq_lens     = (const int*)d_in[4];
    float* out = (float*)d_out;

    const int smem_bytes = SM_TOT * (int)sizeof(float);
    cudaFuncSetAttribute(Model_3470333575380_kernel,
                         cudaFuncAttributeMaxDynamicSharedMemorySize, smem_bytes);

    dim3 grid(NUM_SEQS * NQH * 2 * 2);   // (s, h, qtile, segpair) = 1024
    Model_3470333575380_kernel<<<grid, NTHR, smem_bytes>>>(
        query, key_cache, value_cache, block_tables, seq_lens, out);
}

// round 4
// speedup vs baseline: 1.0011x; 1.0011x over previous
#include <cuda_runtime.h>

// ---------------- static problem config -------------------------------------
#define NUM_SEQS   8
#define QLEN       128
#define NQH        32
#define NKVH       8
#define HDIM       128
#define BLKSZ      16
#define MAXBLOCKS  128
#define NSEG       4
#define SEGTILE    32

// ---------------- tiling ----------------------------------------------------
#define TQ    64      // q rows per CTA
#define TL    64      // keys per stage (4 paged blocks)
#define NTHR  256     // 8 warps

#define QT2S  136     // qT2 row stride (2*64 dup + pad), floats
#define VSS   132     // vs row stride [l][dv], floats

// smem offsets (floats)
#define SM_QT2 0
#define SM_K   (SM_QT2 + HDIM*QT2S)   // 17408
#define SM_V   (SM_K  + HDIM*TL)      // 25600
#define SM_P   (SM_V  + TL*VSS)       // 34048
#define SM_TOT (SM_P  + TL*128)       // 42240 floats = 168960 B

typedef unsigned long long u64;

__device__ __forceinline__ u64 pk2(float a, float b) {
    u64 r; asm("mov.b64 %0,{%1,%2};" : "=l"(r) : "f"(a), "f"(b)); return r;
}
__device__ __forceinline__ void up2(u64 v, float& a, float& b) {
    asm("mov.b64 {%0,%1},%2;" : "=f"(a), "=f"(b) : "l"(v));
}
__device__ __forceinline__ u64 ffma2(u64 a, u64 b, u64 c) {
    u64 d; asm("fma.rn.f32x2 %0,%1,%2,%3;" : "=l"(d) : "l"(a), "l"(b), "l"(c)); return d;
}
__device__ __forceinline__ u64 fmul2(u64 a, u64 b) {
    u64 d; asm("mul.rn.f32x2 %0,%1,%2;" : "=l"(d) : "l"(a), "l"(b)); return d;
}

extern __shared__ float sm[];

__global__ void __launch_bounds__(NTHR, 1) Model_3470333575380_kernel(
    const float* __restrict__ query,
    const float* __restrict__ key_cache,
    const float* __restrict__ value_cache,
    const int*   __restrict__ block_tables,
    const int*   __restrict__ seq_lens,
    float*       __restrict__ out)
{
    const float scale   = 0.08838834764831845f;   // 1/sqrt(128)
    const float softcap = 30.0f;
    const float inv2cap = 2.0f / softcap;

    float* qT2 = sm + SM_QT2;   // [128 d][2*64 q dup]
    float* ks  = sm + SM_K;     // [128 d][64 l], chunk-swizzled by (d&7)
    float* vs  = sm + SM_V;     // [64 l][128 dv + pad]
    float* ps2 = sm + SM_P;     // [64 l][2*64 q dup], chunk-swizzled by ((l>>2)&7)

    const int tid  = threadIdx.x;
    const int lane = tid & 31;
    const int w    = tid >> 5;        // warp id == q-group (8 q rows per warp)

    const int cta = blockIdx.x;
    const int sp  = cta & 1;                  // segment pair {2sp, 2sp+1}
    const int qt  = (cta >> 1) & 1;
    const int h   = (cta >> 2) & (NQH - 1);
    const int s   = cta >> 7;
    const int hkv = h >> 2;

    const int seq_len = seq_lens[s];
    const int ctx     = seq_len - QLEN;
    const int span    = ((seq_len + NSEG*SEGTILE - 1) / (NSEG*SEGTILE)) * SEGTILE; // 512
    const int n_stages = span / TL;           // 8

    const int q0     = qt * TQ;
    const int t_base = s * QLEN + q0;

    // ---- load q tile (pre-scaled), duplicated pairs, [d][2q] ----
    for (int idx = tid; idx < TQ * HDIM; idx += NTHR) {
        int i = idx >> 7;              // q row 0..63
        int d = idx & (HDIM - 1);
        float v = query[((size_t)(t_base + i)*NQH + h)*HDIM + d] * scale;
        qT2[d*QT2S + 2*i]     = v;
        qT2[d*QT2S + 2*i + 1] = v;
    }

    const size_t kv_base4_stride = (size_t)(HDIM * BLKSZ / 4);  // float4 per (blk,head)
    const float4* kc4 = reinterpret_cast<const float4*>(key_cache);
    const float4* vc4 = reinterpret_cast<const float4*>(value_cache);

    u64 accP[8][2];     // 8 q rows x 4 dv (2 pairs); dv = lane*4 .. +3
    float m_prev[8];

    for (int sg = 0; sg < 2; sg++) {
        const int seg = 2*sp + sg;
        #pragma unroll
        for (int qq = 0; qq < 8; qq++) {
            accP[qq][0] = 0ull; accP[qq][1] = 0ull;
            m_prev[qq]  = -1e30f;
        }

        for (int st = 0; st < n_stages; st++) {
            const int l_base = seg * span + st * TL;

            // ---- stage K/V (4 paged blocks of 16 keys) ----
            {
                const int* bt = block_tables + s * MAXBLOCKS + (l_base >> 4);
                #pragma unroll
                for (int it = 0; it < (4*512)/NTHR; it++) {
                    int f  = it * NTHR + tid;      // 0..2047 float4s
                    int j  = f >> 9;               // block 0..3
                    int fi = f & 511;
                    int pb = bt[j];
                    size_t b4 = ((size_t)pb * NKVH + hkv) * kv_base4_stride;
                    int d  = fi >> 2;
                    int cl = fi & 3;
                    float4 k4 = kc4[b4 + fi];
                    int c = (j*4 + cl) ^ (d & 7);
                    *reinterpret_cast<float4*>(ks + d*TL + (c << 2)) = k4;
                    float4 v4 = vc4[b4 + fi];
                    int lr = j*16 + cl*4;
                    vs[(lr+0)*VSS + d] = v4.x;
                    vs[(lr+1)*VSS + d] = v4.y;
                    vs[(lr+2)*VSS + d] = v4.z;
                    vs[(lr+3)*VSS + d] = v4.w;
                }
            }
            __syncthreads();

            // ---- QK: 8q x 2l per thread (l = lane*2, lane*2+1) ----
            u64 acc2[8];
            #pragma unroll
            for (int qq = 0; qq < 8; qq++) acc2[qq] = 0ull;
            {
                const float* qbase = qT2 + w * 16;
                const int koff = (lane & 1) << 1;
                #pragma unroll 4
                for (int d = 0; d < HDIM; d++) {
                    int c = (lane >> 1) ^ (d & 7);
                    u64 k2 = *reinterpret_cast<const u64*>(ks + d*TL + (c << 2) + koff);
                    const float* qr = qbase + d*QT2S;
                    ulonglong2 qa = *reinterpret_cast<const ulonglong2*>(qr);
                    ulonglong2 qb = *reinterpret_cast<const ulonglong2*>(qr + 4);
                    ulonglong2 qc = *reinterpret_cast<const ulonglong2*>(qr + 8);
                    ulonglong2 qd = *reinterpret_cast<const ulonglong2*>(qr + 12);
                    acc2[0] = ffma2(qa.x, k2, acc2[0]);
                    acc2[1] = ffma2(qa.y, k2, acc2[1]);
                    acc2[2] = ffma2(qb.x, k2, acc2[2]);
                    acc2[3] = ffma2(qb.y, k2, acc2[3]);
                    acc2[4] = ffma2(qc.x, k2, acc2[4]);
                    acc2[5] = ffma2(qc.y, k2, acc2[5]);
                    acc2[6] = ffma2(qd.x, k2, acc2[6]);
                    acc2[7] = ffma2(qd.y, k2, acc2[7]);
                }
            }

            // ---- softcap + causal + online max (registers/shuffles only) ----
            float p0a[8], p1a[8], r_[8];
            {
                const int labs0 = l_base + lane*2;
                #pragma unroll
                for (int qq = 0; qq < 8; qq++) {
                    float s0, s1; up2(acc2[qq], s0, s1);
                    float e0 = __expf(s0 * inv2cap);
                    s0 = softcap * __fdividef(e0 - 1.0f, e0 + 1.0f);
                    float e1 = __expf(s1 * inv2cap);
                    s1 = softcap * __fdividef(e1 - 1.0f, e1 + 1.0f);
                    const int kmax = ctx + q0 + w*8 + qq;
                    s0 = (labs0     <= kmax) ? s0 : -3.0e38f;
                    s1 = (labs0 + 1 <= kmax) ? s1 : -3.0e38f;
                    float rm = fmaxf(s0, s1);
                    #pragma unroll
                    for (int o = 16; o >= 1; o >>= 1)
                        rm = fmaxf(rm, __shfl_xor_sync(0xffffffffu, rm, o));
                    float mo = m_prev[qq];
                    float mn = fmaxf(mo, rm);
                    r_[qq] = __expf(mo - mn);
                    m_prev[qq] = mn;
                    p0a[qq] = __expf(s0 - mn);
                    p1a[qq] = __expf(s1 - mn);
                }
            }

            // ---- store p duplicated pairs to ps2 (swizzled) ----
            {
                const int l0 = lane * 2;
                const int sw = (lane >> 1) & 7;       // (l0>>2)&7 == (l1>>2)&7
                float* r0p = ps2 + l0 * 128;
                float* r1p = r0p + 128;
                #pragma unroll
                for (int cc = 0; cc < 4; cc++) {
                    int ch = (((w*4 + cc) ^ sw) << 2);
                    float a0 = p0a[2*cc], b0 = p0a[2*cc+1];
                    float a1 = p1a[2*cc], b1 = p1a[2*cc+1];
                    *reinterpret_cast<float4*>(r0p + ch) = make_float4(a0, a0, b0, b0);
                    *reinterpret_cast<float4*>(r1p + ch) = make_float4(a1, a1, b1, b1);
                }
            }

            // ---- rescale accumulators ----
            #pragma unroll
            for (int qq = 0; qq < 8; qq++) {
                u64 r2 = pk2(r_[qq], r_[qq]);
                accP[qq][0] = fmul2(accP[qq][0], r2);
                accP[qq][1] = fmul2(accP[qq][1], r2);
            }
            __syncthreads();

            // ---- PV: 8q x 4dv per thread (dv = lane*4..+3), over 64 keys ----
            {
                const float* vbase = vs + lane * 4;
                #pragma unroll 2
                for (int l = 0; l < TL; l++) {
                    const int sw = (l >> 2) & 7;
                    const float* pr = ps2 + l * 128;
                    ulonglong2 v2 = *reinterpret_cast<const ulonglong2*>(vbase + l*VSS);
                    u64 pp[8];
                    #pragma unroll
                    for (int cc = 0; cc < 4; cc++) {
                        ulonglong2 t = *reinterpret_cast<const ulonglong2*>(
                            pr + (((w*4 + cc) ^ sw) << 2));
                        pp[2*cc]   = t.x;
                        pp[2*cc+1] = t.y;
                    }
                    #pragma unroll
                    for (int qq = 0; qq < 8; qq++) {
                        accP[qq][0] = ffma2(pp[qq], v2.x, accP[qq][0]);
                        accP[qq][1] = ffma2(pp[qq], v2.y, accP[qq][1]);
                    }
                }
            }
            __syncthreads();
        } // stages

        // ---- write this segment's (unnormalized) accumulator ----
        #pragma unroll
        for (int qq = 0; qq < 8; qq++) {
            int t = t_base + w*8 + qq;
            float4 o;
            up2(accP[qq][0], o.x, o.y);
            up2(accP[qq][1], o.z, o.w);
            *reinterpret_cast<float4*>(
                out + (((size_t)t*NQH + h)*NSEG + seg)*HDIM + lane*4) = o;
        }
    } // segment pair
}

extern "C" void kernel_launch(void* const* d_in, const int* in_sizes, int n_in,
                              void* d_out, int out_size) {
    (void)in_sizes; (void)n_in; (void)out_size;
    const float* query        = (const float*)d_in[0];
    const float* key_cache    = (const float*)d_in[1];
    const float* value_cache  = (const float*)d_in[2];
    const int*   block_tables = (const int*)d_in[3];
    const int*   seq_lens     = (const int*)d_in[4];
    float* out = (float*)d_out;

    const int smem_bytes = SM_TOT * (int)sizeof(float);
    cudaFuncSetAttribute(Model_3470333575380_kernel,
                         cudaFuncAttributeMaxDynamicSharedMemorySize, smem_bytes);

    dim3 grid(NUM_SEQS * NQH * 2 * 2);   // (s, h, qtile, segpair) = 1024
    Model_3470333575380_kernel<<<grid, NTHR, smem_bytes>>>(
        query, key_cache, value_cache, block_tables, seq_lens, out);
}

// round 6
// speedup vs baseline: 2.7939x; 2.7908x over previous
#include <cuda_runtime.h>
#include <cuda_bf16.h>
typedef unsigned int u32;
typedef unsigned long long u64;

#define NUM_SEQS 8
#define QLEN 128
#define NQH 32
#define NKVH 8
#define HDIM 128
#define MAXBLOCKS 128
#define NTHR 256
#define SCALE_F 0.08838834764831845f   // 1/sqrt(128)

// ---- smem layout (bytes). K: [64 l][128 d] bf16 rows padded to 272B.
//                            V: [128 dv][64 l] bf16 rows padded to 144B.
#define KROW 272
#define VROW 144
#define S_KH 0
#define S_KL (S_KH + 64*KROW)      // 17408
#define S_VH (S_KL + 64*KROW)      // 34816
#define S_VL (S_VH + 128*VROW)     // 53248
#define SMEM_BYTES (S_VL + 128*VROW)  // 71680

__device__ __forceinline__ void bsplit(float x, float y, u32& hi, u32& lo){
    __nv_bfloat162 h = __floats2bfloat162_rn(x, y);
    float hx = __low2float(h), hy = __high2float(h);
    __nv_bfloat162 l = __floats2bfloat162_rn(x - hx, y - hy);
    hi = *reinterpret_cast<u32*>(&h);
    lo = *reinterpret_cast<u32*>(&l);
}

__device__ __forceinline__ void mma16816(float* c, const u32* a, u32 b0, u32 b1){
    asm volatile(
        "mma.sync.aligned.m16n8k16.row.col.f32.bf16.bf16.f32 "
        "{%0,%1,%2,%3},{%4,%5,%6,%7},{%8,%9},{%0,%1,%2,%3};"
        : "+f"(c[0]), "+f"(c[1]), "+f"(c[2]), "+f"(c[3])
        : "r"(a[0]), "r"(a[1]), "r"(a[2]), "r"(a[3]), "r"(b0), "r"(b1));
}

extern __shared__ char smem[];

__global__ void __launch_bounds__(NTHR, 1) Model_3470333575380_kernel(
    const float* __restrict__ query, const float* __restrict__ key_cache,
    const float* __restrict__ value_cache, const int* __restrict__ block_tables,
    const int* __restrict__ seq_lens, float* __restrict__ out)
{
    const int tid  = threadIdx.x;
    const int lane = tid & 31;
    const int w    = tid >> 5;      // 8 warps, warp owns q rows w*16 .. w*16+15
    const int g    = lane >> 2;     // fragment row group 0..7
    const int qq   = lane & 3;      // fragment col group 0..3

    const int cta = blockIdx.x;
    const int sp  = cta & 1;                   // segment pair
    const int h   = (cta >> 1) & (NQH - 1);
    const int s   = cta >> 6;
    const int hkv = h >> 2;

    const int seq_len = seq_lens[s];
    const int ctx  = seq_len - QLEN;
    const int span = ((seq_len + 127) / 128) * 32;   // 512
    const int nst  = span / 64;                      // 8

    // ---- Q fragments (hi/lo), resident in registers ----
    u32 qh[8][4], ql[8][4];
    {
        const float* q0 = query + ((size_t)(s*QLEN + w*16 + g)*NQH + h)*HDIM;
        const float* q8 = q0 + (size_t)8*NQH*HDIM;
        #pragma unroll
        for (int ks = 0; ks < 8; ks++){
            int k0 = ks*16 + qq*2;
            float2 x0 = *reinterpret_cast<const float2*>(q0 + k0);
            float2 x1 = *reinterpret_cast<const float2*>(q8 + k0);
            float2 x2 = *reinterpret_cast<const float2*>(q0 + k0 + 8);
            float2 x3 = *reinterpret_cast<const float2*>(q8 + k0 + 8);
            bsplit(x0.x*SCALE_F, x0.y*SCALE_F, qh[ks][0], ql[ks][0]);
            bsplit(x1.x*SCALE_F, x1.y*SCALE_F, qh[ks][1], ql[ks][1]);
            bsplit(x2.x*SCALE_F, x2.y*SCALE_F, qh[ks][2], ql[ks][2]);
            bsplit(x3.x*SCALE_F, x3.y*SCALE_F, qh[ks][3], ql[ks][3]);
        }
    }

    const float4* vc4 = reinterpret_cast<const float4*>(value_cache);
    const int qa0 = ctx + w*16 + g;   // absolute causal bound, row g
    const int qa1 = qa0 + 8;          // row g+8

    for (int sg = 0; sg < 2; sg++){
        const int seg = sp*2 + sg;
        float dacc[16][4];
        #pragma unroll
        for (int i = 0; i < 16; i++)
            #pragma unroll
            for (int j = 0; j < 4; j++) dacc[i][j] = 0.0f;
        float m0 = -1e30f, m1 = -1e30f;

        for (int sti = 0; sti < nst; sti++){
            const int lb = seg*span + sti*64;
            __syncthreads();   // previous stage's smem reads complete

            // ---- stage K: gmem [d][b] -> smem [l][d] bf16 hi/lo ----
            const int* btp = block_tables + s*MAXBLOCKS + (lb >> 4);
            #pragma unroll
            for (int it = 0; it < 8; it++){
                int gg = it*NTHR + tid;
                int l = gg & 63, dc = gg >> 6, d0 = dc*4;
                int pb = btp[l >> 4];
                const float* kb = key_cache + ((size_t)pb*NKVH + hkv)*2048 + (l & 15);
                float x0 = kb[(d0+0)*16], x1 = kb[(d0+1)*16];
                float x2 = kb[(d0+2)*16], x3 = kb[(d0+3)*16];
                u32 hA,lA,hB,lB;
                bsplit(x0,x1,hA,lA); bsplit(x2,x3,hB,lB);
                *reinterpret_cast<u64*>(smem + S_KH + l*KROW + d0*2) = ((u64)hB<<32)|hA;
                *reinterpret_cast<u64*>(smem + S_KL + l*KROW + d0*2) = ((u64)lB<<32)|lA;
            }
            // ---- stage V: gmem [d][b] -> smem [dv][l] bf16 hi/lo (native) ----
            #pragma unroll
            for (int it = 0; it < 8; it++){
                int f = it*NTHR + tid;
                int j = f >> 9, fi = f & 511;
                int pb = btp[j];
                float4 v4 = vc4[((size_t)pb*NKVH + hkv)*512 + fi];
                int d = fi >> 2, c = fi & 3;
                u32 hA,lA,hB,lB;
                bsplit(v4.x,v4.y,hA,lA); bsplit(v4.z,v4.w,hB,lB);
                int off = d*VROW + (j*16 + c*4)*2;
                *reinterpret_cast<u64*>(smem + S_VH + off) = ((u64)hB<<32)|hA;
                *reinterpret_cast<u64*>(smem + S_VL + off) = ((u64)lB<<32)|lA;
            }
            __syncthreads();

            // ---- QK: S[16 x 64] per warp, 3-pass bf16 ----
            float sacc[8][4];
            #pragma unroll
            for (int i = 0; i < 8; i++)
                #pragma unroll
                for (int j = 0; j < 4; j++) sacc[i][j] = 0.0f;
            {
                const char* khb = smem + S_KH + g*KROW + qq*4;
                const char* klb = smem + S_KL + g*KROW + qq*4;
                #pragma unroll
                for (int nt = 0; nt < 8; nt++){
                    int rb = nt*8*KROW;
                    #pragma unroll
                    for (int ks = 0; ks < 8; ks++){
                        int off = rb + ks*32;
                        u32 bh0 = *reinterpret_cast<const u32*>(khb + off);
                        u32 bh1 = *reinterpret_cast<const u32*>(khb + off + 16);
                        u32 bl0 = *reinterpret_cast<const u32*>(klb + off);
                        u32 bl1 = *reinterpret_cast<const u32*>(klb + off + 16);
                        mma16816(sacc[nt], qh[ks], bh0, bh1);
                        mma16816(sacc[nt], ql[ks], bh0, bh1);
                        mma16816(sacc[nt], qh[ks], bl0, bl1);
                    }
                }
            }

            // ---- softcap + causal + p = exp(scv - 30), static max ----
            #pragma unroll
            for (int nt = 0; nt < 8; nt++){
                #pragma unroll
                for (int e = 0; e < 4; e++){
                    int lg  = lb + nt*8 + qq*2 + (e & 1);
                    int row = (e < 2) ? qa0 : qa1;
                    float sv = sacc[nt][e];
                    float ex = __expf(sv * (1.0f/15.0f));       // exp(2s/cap)
                    float u  = __fdividef(60.0f, ex + 1.0f);
                    float scv = 30.0f - u;                      // cap*tanh(s/cap)
                    bool ok = (lg <= row);
                    float p = ok ? __expf(-u) : 0.0f;           // exp(scv-30)
                    if (ok){ if (e < 2) m0 = fmaxf(m0, scv); else m1 = fmaxf(m1, scv); }
                    sacc[nt][e] = p;
                }
            }

            // ---- pack P into A-fragments (hi/lo) for PV ----
            u32 ph[4][4], pl[4][4];
            #pragma unroll
            for (int ks = 0; ks < 4; ks++){
                const float* p0 = sacc[2*ks];
                const float* p1 = sacc[2*ks+1];
                bsplit(p0[0], p0[1], ph[ks][0], pl[ks][0]);
                bsplit(p0[2], p0[3], ph[ks][1], pl[ks][1]);
                bsplit(p1[0], p1[1], ph[ks][2], pl[ks][2]);
                bsplit(p1[2], p1[3], ph[ks][3], pl[ks][3]);
            }

            // ---- PV: D[16 x 128] += P * V, 3-pass bf16 ----
            {
                const char* vhb = smem + S_VH + g*VROW + qq*4;
                const char* vlb = smem + S_VL + g*VROW + qq*4;
                #pragma unroll
                for (int nt = 0; nt < 16; nt++){
                    int rb = nt*8*VROW;
                    #pragma unroll
                    for (int ks = 0; ks < 4; ks++){
                        int off = rb + ks*32;
                        u32 bh0 = *reinterpret_cast<const u32*>(vhb + off);
                        u32 bh1 = *reinterpret_cast<const u32*>(vhb + off + 16);
                        u32 bl0 = *reinterpret_cast<const u32*>(vlb + off);
                        u32 bl1 = *reinterpret_cast<const u32*>(vlb + off + 16);
                        mma16816(dacc[nt], ph[ks], bh0, bh1);
                        mma16816(dacc[nt], pl[ks], bh0, bh1);
                        mma16816(dacc[nt], ph[ks], bl0, bl1);
                    }
                }
            }
        } // stages

        // ---- finalize segment: scale by exp(30 - m), write out ----
        #pragma unroll
        for (int o = 1; o <= 2; o <<= 1){
            m0 = fmaxf(m0, __shfl_xor_sync(0xffffffffu, m0, o));
            m1 = fmaxf(m1, __shfl_xor_sync(0xffffffffu, m1, o));
        }
        float sc0 = (m0 > -100.0f) ? __expf(30.0f - m0) : 0.0f;
        float sc1 = (m1 > -100.0f) ? __expf(30.0f - m1) : 0.0f;

        const int t0 = s*QLEN + w*16 + g;
        float* o0 = out + (((size_t)t0*NQH + h)*4 + seg)*HDIM;
        float* o1 = o0 + (size_t)8*NQH*4*HDIM;
        #pragma unroll
        for (int nt = 0; nt < 16; nt++){
            int dv = nt*8 + qq*2;
            float2 a = make_float2(dacc[nt][0]*sc0, dacc[nt][1]*sc0);
            float2 b = make_float2(dacc[nt][2]*sc1, dacc[nt][3]*sc1);
            *reinterpret_cast<float2*>(o0 + dv) = a;
            *reinterpret_cast<float2*>(o1 + dv) = b;
        }
    } // segments
}

extern "C" void kernel_launch(void* const* d_in, const int* in_sizes, int n_in,
                              void* d_out, int out_size) {
    (void)in_sizes; (void)n_in; (void)out_size;
    const float* query        = (const float*)d_in[0];
    const float* key_cache    = (const float*)d_in[1];
    const float* value_cache  = (const float*)d_in[2];
    const int*   block_tables = (const int*)d_in[3];
    const int*   seq_lens     = (const int*)d_in[4];
    float* out = (float*)d_out;

    cudaFuncSetAttribute(Model_3470333575380_kernel,
                         cudaFuncAttributeMaxDynamicSharedMemorySize, SMEM_BYTES);
    Model_3470333575380_kernel<<<NUM_SEQS*NQH*2, NTHR, SMEM_BYTES>>>(
        query, key_cache, value_cache, block_tables, seq_lens, out);
}